// round 13
// baseline (speedup 1.0000x reference)
#include <cuda_runtime.h>
#include <cuda_fp16.h>
#include <cstddef>

#define NB     2
#define N_IN   163842
#define N_OUT  40962
#define CDIM   128
#define KCAND  7

// Scratch (static device globals — no runtime allocation).
// Pooled weighted sums accumulate directly in fp16 (atomic f16x2 reductions).
__device__ __half g_down_h[(size_t)NB * N_OUT * CDIM];   // 21 MB
__device__ float  g_denom[N_OUT];

// ---------------------------------------------------------------------------
// Kernel 0: zero fp16 scratch + denom (R8 form — fastest measured at 7.1us;
// both the 64B/thread variant and driver memset nodes were slower).
// ---------------------------------------------------------------------------
__global__ void __launch_bounds__(256) zero_kernel() {
    const size_t total16 = (size_t)NB * N_OUT * CDIM * sizeof(__half) / 16;
    const size_t stride  = (size_t)gridDim.x * blockDim.x;
    for (size_t i = (size_t)blockIdx.x * blockDim.x + threadIdx.x;
         i < total16; i += stride) {
        uint4 z; z.x = 0u; z.y = 0u; z.z = 0u; z.w = 0u;
        reinterpret_cast<uint4*>(g_down_h)[i] = z;
    }
    const size_t t = (size_t)blockIdx.x * blockDim.x + threadIdx.x;
    if (t < N_OUT) g_denom[t] = 0.f;
}

// ---------------------------------------------------------------------------
// Kernel 1: scatter-add in fp16 (unchanged):
//   down_h[b, parent[n], :] += fp16(omega[n] * x[b, n, :])
//   denom[parent[n]]        += omega[n]
// One warp per input row n; lanes 0-15 -> b=0, lanes 16-31 -> b=1; each lane
// covers 8 channels: 2x LDG.128 + pack + red.global.add.noftz.v4.f16x2.
// ---------------------------------------------------------------------------
__global__ void __launch_bounds__(256) scatter_kernel(
        const float* __restrict__ x,
        const float* __restrict__ omega,
        const int*   __restrict__ parent) {
    const int warp = (int)(((size_t)blockIdx.x * blockDim.x + threadIdx.x) >> 5);
    const int lane = threadIdx.x & 31;
    if (warp >= N_IN) return;

    const int   p  = parent[warp];   // broadcast
    const float om = omega[warp];    // broadcast

    const int sub = lane >> 4;       // batch
    const int li  = lane & 15;       // 16B slot (8 channels) within the row

    const float4* xr =
        reinterpret_cast<const float4*>(x + ((size_t)sub * N_IN + warp) * CDIM)
        + li * 2;
    float4 a = xr[0];
    float4 b = xr[1];
    a.x *= om; a.y *= om; a.z *= om; a.w *= om;
    b.x *= om; b.y *= om; b.z *= om; b.w *= om;

    __half2 h0 = __floats2half2_rn(a.x, a.y);
    __half2 h1 = __floats2half2_rn(a.z, a.w);
    __half2 h2 = __floats2half2_rn(b.x, b.y);
    __half2 h3 = __floats2half2_rn(b.z, b.w);

    __half* dst = g_down_h + ((size_t)sub * N_OUT + p) * CDIM + li * 8;
    asm volatile("red.global.add.noftz.v4.f16x2 [%0], {%1, %2, %3, %4};"
                 :: "l"(dst),
                    "r"(*reinterpret_cast<unsigned*>(&h0)),
                    "r"(*reinterpret_cast<unsigned*>(&h1)),
                    "r"(*reinterpret_cast<unsigned*>(&h2)),
                    "r"(*reinterpret_cast<unsigned*>(&h3))
                 : "memory");

    if (lane == 0) {
        atomicAdd(&g_denom[p], om);
    }
}

// ---------------------------------------------------------------------------
// Kernel 2: gather — single-line LDG.32 restructure.
// Profile showed L1tex=74.6% is the binder; multi-line LDG.128 wavefronts
// replay at ~2.07 cyc/wf, single-line LDGs stream at ~1.0. Per candidate k:
// 4x LDG.32 (32 lanes x 4B consecutive = exactly one 128B line each; two per
// 256B row x two batches) = 4 wf @1.0 vs the old 4 wf @2.07.
// Each lane owns fp16 channel pairs (2*lane) and (64+2*lane) for BOTH
// batches; dual interleaved HFMA2 partials (chains <= 4), f32 finalize,
// 4x STG.64 out (float2 per lane per half-row per batch).
// Weight phase unchanged: lanes 0-6 one candidate each, width-8 butterfly,
// denom folded, clamp (zero-parent rows are all-zero -> clamp exact).
// ---------------------------------------------------------------------------
__global__ void __launch_bounds__(256) gather_kernel(
        const float* __restrict__ delta,
        const float* __restrict__ mask,
        const int*   __restrict__ cand,
        float*       __restrict__ out) {
    const int warp = (int)(((size_t)blockIdx.x * blockDim.x + threadIdx.x) >> 5);
    const int lane = threadIdx.x & 31;
    if (warp >= N_IN) return;

    const float INV2S2 = 3.125f;  // 1 / (2 * 0.4^2)

    // ---- lanes 0-6: per-candidate weight ----
    float w = 0.f;
    int   c = 0;
    if (lane < KCAND) {
        const size_t o = (size_t)warp * KCAND + lane;
        const float d = delta[o];
        const float m = mask[o];
        c = cand[o];
        w = __expf(-d * d * INV2S2) * m;
    }
    float s = w;
    s += __shfl_down_sync(0xffffffffu, s, 4, 8);
    s += __shfl_down_sync(0xffffffffu, s, 2, 8);
    s += __shfl_down_sync(0xffffffffu, s, 1, 8);
    s  = __shfl_sync(0xffffffffu, s, 0, 8);

    unsigned whbits = 0;
    if (lane < KCAND) {
        const float den = fmaxf(__ldg(&g_denom[c]), 1e-8f);
        float wf = w / (fmaxf(s, 1e-8f) * den);
        wf = fminf(wf, 1000.0f);
        const __half2 wh = __float2half2_rn(wf);
        whbits = *reinterpret_cast<const unsigned*>(&wh);
    }

    // ---- accumulation: 4x single-line LDG.32 per candidate ----
    const __half2 hz = __float2half2_rn(0.f);
    // acc[parity][batch][half-of-row]
    __half2 aA00 = hz, aA01 = hz, aA10 = hz, aA11 = hz;
    __half2 aB00 = hz, aB01 = hz, aB10 = hz, aB11 = hz;

#pragma unroll
    for (int k = 0; k < KCAND; ++k) {
        const unsigned wb = __shfl_sync(0xffffffffu, whbits, k);
        const int      ik = __shfl_sync(0xffffffffu, c, k);
        const __half2  wh = *reinterpret_cast<const __half2*>(&wb);

        const unsigned* r0 = reinterpret_cast<const unsigned*>(
            g_down_h + (size_t)ik * CDIM);                    // batch 0 row
        const unsigned* r1 = reinterpret_cast<const unsigned*>(
            g_down_h + ((size_t)N_OUT + ik) * CDIM);          // batch 1 row

        // Each load: 32 lanes x 4B consecutive = one 128B line.
        const unsigned u00 = __ldg(r0 + lane);        // b0, ch 2*lane
        const unsigned u01 = __ldg(r0 + 32 + lane);   // b0, ch 64+2*lane
        const unsigned u10 = __ldg(r1 + lane);        // b1, ch 2*lane
        const unsigned u11 = __ldg(r1 + 32 + lane);   // b1, ch 64+2*lane

        const __half2 h00 = *reinterpret_cast<const __half2*>(&u00);
        const __half2 h01 = *reinterpret_cast<const __half2*>(&u01);
        const __half2 h10 = *reinterpret_cast<const __half2*>(&u10);
        const __half2 h11 = *reinterpret_cast<const __half2*>(&u11);

        if ((k & 1) == 0) {
            aA00 = __hfma2(h00, wh, aA00);
            aA01 = __hfma2(h01, wh, aA01);
            aA10 = __hfma2(h10, wh, aA10);
            aA11 = __hfma2(h11, wh, aA11);
        } else {
            aB00 = __hfma2(h00, wh, aB00);
            aB01 = __hfma2(h01, wh, aB01);
            aB10 = __hfma2(h10, wh, aB10);
            aB11 = __hfma2(h11, wh, aB11);
        }
    }

    // ---- finalize in f32, store: float2 per lane per half-row per batch ----
    const float2 f00a = __half22float2(aA00), f00b = __half22float2(aB00);
    const float2 f01a = __half22float2(aA01), f01b = __half22float2(aB01);
    const float2 f10a = __half22float2(aA10), f10b = __half22float2(aB10);
    const float2 f11a = __half22float2(aA11), f11b = __half22float2(aB11);

    float* base0 = out + ((size_t)0 * N_IN + warp) * CDIM;
    float* base1 = out + ((size_t)1 * N_IN + warp) * CDIM;

    reinterpret_cast<float2*>(base0)[lane] =
        make_float2(f00a.x + f00b.x, f00a.y + f00b.y);        // b0 ch 2l..
    reinterpret_cast<float2*>(base0)[32 + lane] =
        make_float2(f01a.x + f01b.x, f01a.y + f01b.y);        // b0 ch 64+2l..
    reinterpret_cast<float2*>(base1)[lane] =
        make_float2(f10a.x + f10b.x, f10a.y + f10b.y);        // b1 ch 2l..
    reinterpret_cast<float2*>(base1)[32 + lane] =
        make_float2(f11a.x + f11b.x, f11a.y + f11b.y);        // b1 ch 64+2l..
}

// ---------------------------------------------------------------------------
// Launcher. Input order: x, omega, delta, cand_mask, parent_idx, cand_idx.
// Output: float32 (B, N_IN, C). Single stream.
// ---------------------------------------------------------------------------
extern "C" void kernel_launch(void* const* d_in, const int* in_sizes, int n_in,
                              void* d_out, int out_size) {
    const float* x      = (const float*)d_in[0];
    const float* omega  = (const float*)d_in[1];
    const float* delta  = (const float*)d_in[2];
    const float* mask   = (const float*)d_in[3];
    const int*   parent = (const int*)d_in[4];
    const int*   cand   = (const int*)d_in[5];
    float*       out    = (float*)d_out;

    (void)in_sizes; (void)n_in; (void)out_size;

    // Zero fp16 scratch + denom
    {
        const size_t total16 = (size_t)NB * N_OUT * CDIM * sizeof(__half) / 16;
        const int threads = 256;
        const int blocks  = (int)((total16 + threads - 1) / threads);
        zero_kernel<<<blocks, threads>>>();
    }
    // Scatter pool (fp16 vector reductions)
    {
        const int threads = 256;  // 8 warps / block
        const int blocks  = (N_IN + 8 - 1) / 8;
        scatter_kernel<<<blocks, threads>>>(x, omega, parent);
    }
    // Gather + weight (single-line LDG.32 loads, HFMA2 accumulate)
    {
        const int threads = 256;
        const int blocks  = (N_IN + 8 - 1) / 8;
        gather_kernel<<<blocks, threads>>>(delta, mask, cand, out);
    }
}